// round 1
// baseline (speedup 1.0000x reference)
#include <cuda_runtime.h>

#define T_STEPS 4096
#define BATCH 64
#define IN_DIM 4
#define HID 256
#define OUT_DIM 2

// hidden-state history for the output head: [T, B, H] fp32 = 268 MB scratch
__device__ float g_hs[(size_t)T_STEPS * BATCH * HID];

__device__ __forceinline__ void fma2(unsigned long long &acc,
                                     unsigned long long a,
                                     unsigned long long b) {
    // packed fp32x2 FMA (sm_100+): 2 MACs per issue
    asm("fma.rn.f32x2 %0, %1, %2, %0;" : "+l"(acc) : "l"(a), "l"(b));
}

__device__ __forceinline__ float2 unpack2(unsigned long long v) {
    float2 f;
    asm("mov.b64 {%0, %1}, %2;" : "=f"(f.x), "=f"(f.y) : "l"(v));
    return f;
}

__device__ __forceinline__ unsigned int smem_u32(const void* p) {
    unsigned int a;
    asm("{ .reg .u64 t; cvta.to.shared.u64 t, %1; cvt.u32.u64 %0, t; }"
        : "=r"(a) : "l"(p));
    return a;
}

// ---------------------------------------------------------------------------
// Recurrence kernel: 64 clusters x 2 CTAs x 256 threads.
// Cluster c handles batch b = c. CTA rank r computes h outputs [128r, 128r+128).
// Thread t: output j_local = t & 127, K-half = t >> 7. Its 128 Wh weights live
// in registers as 64 packed f32x2 values for the whole 4096-step loop.
// h (256 floats) lives double-buffered in SMEM; halves are exchanged via
// st.shared::cluster + a cluster barrier each step.
// ---------------------------------------------------------------------------
__global__ void __launch_bounds__(256, 1) __cluster_dims__(2, 1, 1)
elman_recurrence(const float* __restrict__ input,
                 const float* __restrict__ Wi,
                 const float* __restrict__ bi,
                 const float* __restrict__ Wh,
                 const float* __restrict__ bh) {
    __shared__ float hbuf[2][HID];
    __shared__ float p1s[128];

    const int tid  = threadIdx.x;
    const int rank = blockIdx.x & 1;          // cluster_ctarank
    const int b    = blockIdx.x >> 1;         // batch element
    const int jl   = tid & 127;               // local output index
    const int half = tid >> 7;                // K-half (0: k<128, 1: k>=128)
    const int jg   = rank * 128 + jl;         // global output index

    // --- load this thread's 128 Wh weights into registers (loop-invariant) ---
    unsigned long long wh[64];
    {
        const ulonglong2* wsrc =
            (const ulonglong2*)(Wh + (size_t)jg * HID + half * 128);
#pragma unroll
        for (int m = 0; m < 32; ++m) {
            ulonglong2 v = __ldg(wsrc + m);
            wh[2 * m]     = v.x;   // packs Wh[jg][4m], Wh[jg][4m+1]
            wh[2 * m + 1] = v.y;   // packs Wh[jg][4m+2], Wh[jg][4m+3]
        }
    }

    // --- epilogue-thread constants: Wi row, bi+bh ---
    float4 wi4 = make_float4(0.f, 0.f, 0.f, 0.f);
    float  cb  = 0.f;
    if (tid < 128) {
        wi4 = __ldg((const float4*)(Wi + (size_t)jg * IN_DIM));
        cb  = __ldg(bi + jg) + __ldg(bh + jg);
    }

    // --- peer-CTA SMEM addresses for my h slot in both buffers ---
    unsigned int raddr0 = 0, raddr1 = 0;
    if (tid < 128) {
        unsigned int l0 = smem_u32(&hbuf[0][jg]);
        unsigned int l1 = smem_u32(&hbuf[1][jg]);
        unsigned int peer = rank ^ 1;
        asm("mapa.shared::cluster.u32 %0, %1, %2;" : "=r"(raddr0) : "r"(l0), "r"(peer));
        asm("mapa.shared::cluster.u32 %0, %1, %2;" : "=r"(raddr1) : "r"(l1), "r"(peer));
    }

    // --- h0 = 0 ---
    if (tid < HID) hbuf[0][tid] = 0.f;
    asm volatile("barrier.cluster.arrive.aligned;" ::: "memory");
    asm volatile("barrier.cluster.wait.aligned;" ::: "memory");

    // prefetch input for t=0
    float4 xin = make_float4(0.f, 0.f, 0.f, 0.f);
    if (tid < 128)
        xin = __ldg((const float4*)(input + (size_t)b * IN_DIM));

    float* hsb = g_hs + (size_t)b * HID;

    for (int t = 0; t < T_STEPS; ++t) {
        // prefetch next step's input early (hides DRAM/L2 latency)
        float4 xnext = xin;
        if (tid < 128 && t + 1 < T_STEPS)
            xnext = __ldg((const float4*)(input +
                          ((size_t)(t + 1) * BATCH + b) * IN_DIM));

        const int cur = t & 1;
        const ulonglong2* h2 = ((const ulonglong2*)hbuf[cur]) + half * 32;

        unsigned long long a0 = 0ull, a1 = 0ull, a2 = 0ull, a3 = 0ull;
#pragma unroll
        for (int m = 0; m < 32; m += 2) {
            ulonglong2 hm0 = h2[m];        // broadcast LDS.128
            fma2(a0, wh[2 * m],     hm0.x);
            fma2(a1, wh[2 * m + 1], hm0.y);
            ulonglong2 hm1 = h2[m + 1];
            fma2(a2, wh[2 * m + 2], hm1.x);
            fma2(a3, wh[2 * m + 3], hm1.y);
        }
        float2 f0 = unpack2(a0), f1 = unpack2(a1);
        float2 f2 = unpack2(a2), f3 = unpack2(a3);
        float partial = ((f0.x + f0.y) + (f1.x + f1.y)) +
                        ((f2.x + f2.y) + (f3.x + f3.y));

        if (tid >= 128) p1s[jl] = partial;   // half-1 partials to SMEM
        __syncthreads();

        if (tid < 128) {
            float s = partial + p1s[jl] +
                      xin.x * wi4.x + xin.y * wi4.y +
                      xin.z * wi4.z + xin.w * wi4.w + cb;
            float hn = tanhf(s);
            hbuf[cur ^ 1][jg] = hn;                     // local h_next
            unsigned int ra = (cur ^ 1) ? raddr1 : raddr0;
            asm volatile("st.shared::cluster.f32 [%0], %1;"
                         :: "r"(ra), "f"(hn) : "memory");   // peer h_next
            hsb[(size_t)t * (BATCH * HID) + jg] = hn;   // stream hs (off-path)
        }
        xin = xnext;

        // release my writes / acquire peer's writes for next step
        asm volatile("barrier.cluster.arrive.aligned;" ::: "memory");
        asm volatile("barrier.cluster.wait.aligned;" ::: "memory");
    }
}

// ---------------------------------------------------------------------------
// Output head: out[t,b,:] = tanh(hs[t,b,:] @ Wf^T + bf). One warp per row,
// grid-stride. Memory-bound: streams 268 MB of hs.
// ---------------------------------------------------------------------------
__global__ void __launch_bounds__(256)
elman_head(const float* __restrict__ Wf,
           const float* __restrict__ bf,
           float* __restrict__ out) {
    const int lane   = threadIdx.x & 31;
    const int gwarp  = (blockIdx.x * blockDim.x + threadIdx.x) >> 5;
    const int nwarps = (gridDim.x * blockDim.x) >> 5;

    const float bf0 = __ldg(bf + 0);
    const float bf1 = __ldg(bf + 1);

    // each lane owns 8 consecutive h columns: [lane*8, lane*8+8)
    const float4* wf0p = (const float4*)(Wf) + lane * 2;
    const float4* wf1p = (const float4*)(Wf + HID) + lane * 2;
    const float4 w00 = __ldg(wf0p), w01 = __ldg(wf0p + 1);
    const float4 w10 = __ldg(wf1p), w11 = __ldg(wf1p + 1);

    const int nrows = T_STEPS * BATCH;
    for (int row = gwarp; row < nrows; row += nwarps) {
        const float4* h = (const float4*)(g_hs + (size_t)row * HID) + lane * 2;
        float4 h0 = h[0], h1 = h[1];
        float s0 = h0.x * w00.x + h0.y * w00.y + h0.z * w00.z + h0.w * w00.w +
                   h1.x * w01.x + h1.y * w01.y + h1.z * w01.z + h1.w * w01.w;
        float s1 = h0.x * w10.x + h0.y * w10.y + h0.z * w10.z + h0.w * w10.w +
                   h1.x * w11.x + h1.y * w11.y + h1.z * w11.z + h1.w * w11.w;
#pragma unroll
        for (int o = 16; o; o >>= 1) {
            s0 += __shfl_xor_sync(0xffffffffu, s0, o);
            s1 += __shfl_xor_sync(0xffffffffu, s1, o);
        }
        if (lane == 0) {
            out[(size_t)row * OUT_DIM + 0] = tanhf(s0 + bf0);
            out[(size_t)row * OUT_DIM + 1] = tanhf(s1 + bf1);
        }
    }
}

extern "C" void kernel_launch(void* const* d_in, const int* in_sizes, int n_in,
                              void* d_out, int out_size) {
    // metadata order = reference signature order:
    // input, target, Wi, bi, Wh, bh, Wf, bf
    const float* input = (const float*)d_in[0];
    // d_in[1] = target (unused by forward pass)
    const float* Wi = (const float*)d_in[2];
    const float* bi = (const float*)d_in[3];
    const float* Wh = (const float*)d_in[4];
    const float* bh = (const float*)d_in[5];
    const float* Wf = (const float*)d_in[6];
    const float* bf = (const float*)d_in[7];
    float* out = (float*)d_out;

    // 64 clusters of 2 CTAs (cluster dims baked via __cluster_dims__)
    elman_recurrence<<<2 * BATCH, 256>>>(input, Wi, bi, Wh, bh);
    elman_head<<<512, 256>>>(Wf, bf, out);
}